// round 6
// baseline (speedup 1.0000x reference)
#include <cuda_runtime.h>

#define TT 512
#define DD 16
#define HH 48
#define NB 16
#define NTHREADS 384
#define NCTA 128

typedef unsigned long long ull;

__device__ __forceinline__ float fsig(float x) {
    return __fdividef(1.0f, 1.0f + __expf(-x));
}
__device__ __forceinline__ float ftanh_(float x) {
    return __fdividef(2.0f, 1.0f + __expf(-2.0f * x)) - 1.0f;
}
__device__ __forceinline__ void ffma2(ull& a, ull w, ull h) {
    asm("fma.rn.f32x2 %0, %1, %2, %0;" : "+l"(a) : "l"(w), "l"(h));
}
__device__ __forceinline__ float2 unpk(ull v) {
    float2 r;
    asm("mov.b64 {%0, %1}, %2;" : "=f"(r.x), "=f"(r.y) : "l"(v));
    return r;
}
__device__ __forceinline__ ull pk2(float a, float b) {
    ull d;
    asm("mov.b64 %0, {%1, %2};" : "=l"(d) : "f"(a), "f"(b));
    return d;
}

// Reduction + activation + h-store for one 8-bb half of one layer.
// acc[b8][g01]: k-parity-packed partial gate sums (this thread's kq slice).
__device__ __forceinline__ void epilogue(
    ull (&acc)[8][2], int half, float* cst, float* hdst,
    int kq, int gp, int posj)
{
    // horizontal add (lo = even-k sum, hi = odd-k sum)
    float v[8][2];
    #pragma unroll
    for (int b8 = 0; b8 < 8; ++b8) {
        float2 u0 = unpk(acc[b8][0]); v[b8][0] = u0.x + u0.y;
        float2 u1 = unpk(acc[b8][1]); v[b8][1] = u1.x + u1.y;
    }
    // butterfly reduce over kq lanes (bits 0,1)
    #pragma unroll
    for (int b8 = 0; b8 < 8; ++b8) {
        v[b8][0] += __shfl_xor_sync(0xFFFFFFFFu, v[b8][0], 1);
        v[b8][1] += __shfl_xor_sync(0xFFFFFFFFu, v[b8][1], 1);
        v[b8][0] += __shfl_xor_sync(0xFFFFFFFFu, v[b8][0], 2);
        v[b8][1] += __shfl_xor_sync(0xFFFFFFFFu, v[b8][1], 2);
    }
    // static select: S0 = v[kq] (gp0 block), S1 = v[4+kq] (gp1 block)
    float S0[2], S1[2];
    #pragma unroll
    for (int g01 = 0; g01 < 2; ++g01) {
        float a = (kq & 1) ? v[1][g01] : v[0][g01];
        float b = (kq & 1) ? v[3][g01] : v[2][g01];
        S0[g01] = (kq & 2) ? b : a;
        float d = (kq & 1) ? v[5][g01] : v[4][g01];
        float e = (kq & 1) ? v[7][g01] : v[6][g01];
        S1[g01] = (kq & 2) ? e : d;
    }
    float mine0 = gp ? S1[0] : S0[0];
    float mine1 = gp ? S1[1] : S0[1];
    float send0 = gp ? S0[0] : S1[0];
    float send1 = gp ? S0[1] : S1[1];
    float r0 = __shfl_xor_sync(0xFFFFFFFFu, send0, 4);
    float r1 = __shfl_xor_sync(0xFFFFFFFFu, send1, 4);
    // gp==0 holds (i,f), receives (g,o); gp==1 holds (g,o), receives (i,f)
    float gi = gp ? r0 : mine0;
    float gf = gp ? r1 : mine1;
    float gg = gp ? mine0 : r0;
    float go = gp ? mine1 : r1;
    float iv = fsig(gi), fv = fsig(gf), gv = ftanh_(gg), ov = fsig(go);
    float c = fmaf(fv, cst[half], iv * gv);
    cst[half] = c;
    int bb = half * 8 + gp * 4 + kq;
    hdst[bb * HH + posj] = ov * ftanh_(c);
}

__global__ void __launch_bounds__(NTHREADS, 1)
lstm2_kernel(const float* __restrict__ x,
             const float* __restrict__ Wih0, const float* __restrict__ Whh0,
             const float* __restrict__ bih0, const float* __restrict__ bhh0,
             const float* __restrict__ Wih1, const float* __restrict__ Whh1,
             const float* __restrict__ bih1, const float* __restrict__ bhh1,
             const float* __restrict__ fcw,  const float* __restrict__ fcb,
             float* __restrict__ out)
{
    // h row layout: float index = i*16 + kq*4 + c, where k = kq*12 + i*4 + c
    __shared__ __align__(16) float h1s[2][NB][HH];
    __shared__ __align__(16) float h2s[2][NB][HH];
    __shared__ __align__(16) float xs[2][NB][DD];   // natural k order
    __shared__ float fcws[HH];

    const int tid = threadIdx.x;
    const int kq = tid & 3;
    const int gp = (tid >> 2) & 1;
    const int j  = tid >> 3;          // 0..47

    for (int i = tid; i < 2*NB*HH; i += NTHREADS) {
        (&h1s[0][0][0])[i] = 0.f;
        (&h2s[0][0][0])[i] = 0.f;
    }
    if (tid < HH) {
        int pj = ((tid % 12) >> 2) * 16 + (tid / 12) * 4 + (tid & 3);
        fcws[pj] = fcw[tid];
    }
    const float* xg = x + (long)(blockIdx.x * NB) * (long)(TT * DD);
    if (tid < NB * DD)
        xs[0][tid >> 4][tid & 15] = xg[(long)(tid >> 4) * (TT * DD) + (tid & 15)];

    // ---- weights to registers (loop-invariant) ----
    ull wA[2][6], wB[2][6], wC[2][6], wI[2][2], bL1[2], bL2[2];
    #pragma unroll
    for (int g01 = 0; g01 < 2; ++g01) {
        const int gate = gp * 2 + g01;
        const float* rA = Whh0 + (gate * HH + j) * HH + kq * 12;
        const float* rB = Wih1 + (gate * HH + j) * HH + kq * 12;
        const float* rC = Whh1 + (gate * HH + j) * HH + kq * 12;
        #pragma unroll
        for (int kp = 0; kp < 6; ++kp) {
            wA[g01][kp] = pk2(rA[2*kp], rA[2*kp + 1]);
            wB[g01][kp] = pk2(rB[2*kp], rB[2*kp + 1]);
            wC[g01][kp] = pk2(rC[2*kp], rC[2*kp + 1]);
        }
        const float* rI = Wih0 + (gate * HH + j) * DD + kq * 4;
        wI[g01][0] = pk2(rI[0], rI[1]);
        wI[g01][1] = pk2(rI[2], rI[3]);
        float b1 = (kq == 0) ? (bih0[gate * HH + j] + bhh0[gate * HH + j]) : 0.f;
        float b2 = (kq == 0) ? (bih1[gate * HH + j] + bhh1[gate * HH + j]) : 0.f;
        bL1[g01] = pk2(b1, 0.f);
        bL2[g01] = pk2(b2, 0.f);
    }

    float c1[2] = {0.f, 0.f};
    float c2[2] = {0.f, 0.f};
    const int posj = ((j % 12) >> 2) * 16 + (j / 12) * 4 + (j & 3);
    __syncthreads();

    for (int t = 0; t < TT; ++t) {
        const int cur = t & 1, nxt = cur ^ 1;

        // prefetch x[t+1] (LDG overlaps whole step)
        float xpre = 0.f;
        if (t + 1 < TT && tid < NB * DD)
            xpre = xg[(long)(tid >> 4) * (TT * DD) + (long)(t + 1) * DD + (tid & 15)];

        // ================= layer 1 : h1[t] = f(x[t], h1[t-1]) =================
        {
            const float* h1p = &h1s[nxt][0][0] + kq * 4;
            const float* xb  = &xs[cur][0][0]  + kq * 4;
            #pragma unroll
            for (int half = 0; half < 2; ++half) {
                ull acc[8][2];
                #pragma unroll
                for (int b8 = 0; b8 < 8; ++b8) { acc[b8][0] = bL1[0]; acc[b8][1] = bL1[1]; }
                #pragma unroll
                for (int b8 = 0; b8 < 8; ++b8) {
                    const int bb = half * 8 + b8;
                    const ulonglong2 xv = *(const ulonglong2*)(xb + bb * DD);
                    ffma2(acc[b8][0], wI[0][0], xv.x); ffma2(acc[b8][0], wI[0][1], xv.y);
                    ffma2(acc[b8][1], wI[1][0], xv.x); ffma2(acc[b8][1], wI[1][1], xv.y);
                    #pragma unroll
                    for (int i = 0; i < 3; ++i) {
                        const ulonglong2 hv = *(const ulonglong2*)(h1p + bb * HH + i * 16);
                        ffma2(acc[b8][0], wA[0][2*i], hv.x); ffma2(acc[b8][0], wA[0][2*i+1], hv.y);
                        ffma2(acc[b8][1], wA[1][2*i], hv.x); ffma2(acc[b8][1], wA[1][2*i+1], hv.y);
                    }
                }
                epilogue(acc, half, c1, &h1s[cur][0][0], kq, gp, posj);
            }
        }
        __syncthreads();   // h1[t] visible

        // ================= layer 2 : h2[t] = f(h1[t], h2[t-1]) =================
        {
            const float* h1n = &h1s[cur][0][0] + kq * 4;
            const float* h2p = &h2s[nxt][0][0] + kq * 4;
            #pragma unroll
            for (int half = 0; half < 2; ++half) {
                ull acc[8][2];
                #pragma unroll
                for (int b8 = 0; b8 < 8; ++b8) { acc[b8][0] = bL2[0]; acc[b8][1] = bL2[1]; }
                #pragma unroll
                for (int b8 = 0; b8 < 8; ++b8) {
                    const int bb = half * 8 + b8;
                    #pragma unroll
                    for (int i = 0; i < 3; ++i) {
                        const ulonglong2 hv = *(const ulonglong2*)(h1n + bb * HH + i * 16);
                        ffma2(acc[b8][0], wB[0][2*i], hv.x); ffma2(acc[b8][0], wB[0][2*i+1], hv.y);
                        ffma2(acc[b8][1], wB[1][2*i], hv.x); ffma2(acc[b8][1], wB[1][2*i+1], hv.y);
                    }
                    #pragma unroll
                    for (int i = 0; i < 3; ++i) {
                        const ulonglong2 hv = *(const ulonglong2*)(h2p + bb * HH + i * 16);
                        ffma2(acc[b8][0], wC[0][2*i], hv.x); ffma2(acc[b8][0], wC[0][2*i+1], hv.y);
                        ffma2(acc[b8][1], wC[1][2*i], hv.x); ffma2(acc[b8][1], wC[1][2*i+1], hv.y);
                    }
                }
                epilogue(acc, half, c2, &h2s[cur][0][0], kq, gp, posj);
            }
        }

        // stage prefetched x[t+1]
        if (t + 1 < TT && tid < NB * DD)
            xs[nxt][tid >> 4][tid & 15] = xpre;
        __syncthreads();   // h2[t], x[t+1] visible
    }

    // ===== final FC + sigmoid: h2[511] in buf 1 (permuted row layout) =====
    if (tid < NB) {
        const float* hf = &h2s[1][tid][0];
        float acc = fcb[0];
        #pragma unroll
        for (int jj = 0; jj < HH; ++jj)
            acc = fmaf(hf[jj], fcws[jj], acc);
        out[blockIdx.x * NB + tid] = fsig(acc);
    }
}

extern "C" void kernel_launch(void* const* d_in, const int* in_sizes, int n_in,
                              void* d_out, int out_size) {
    (void)in_sizes; (void)n_in; (void)out_size;
    lstm2_kernel<<<NCTA, NTHREADS>>>(
        (const float*)d_in[0],
        (const float*)d_in[1], (const float*)d_in[2],
        (const float*)d_in[3], (const float*)d_in[4],
        (const float*)d_in[5], (const float*)d_in[6],
        (const float*)d_in[7], (const float*)d_in[8],
        (const float*)d_in[9], (const float*)d_in[10],
        (float*)d_out);
}

// round 8
// speedup vs baseline: 1.1060x; 1.1060x over previous
#include <cuda_runtime.h>

// Problem constants
#define TT 512
#define DD 16
#define HH 48
#define NB 16
#define NBI 4
#define NTHREADS 384
#define NCTA 128

typedef unsigned long long ull;

// SMEM byte offsets
#define W1I_B 0                   // [8 kp][96 jj2][16B]
#define WR_B  12288               // [24 kp][96 jj2][3 mat][16B]
#define BB1_B 122880              // [96 jj2][16B] {b_g0,0,b_g1,0}
#define BB2_B 124416
#define H1_B  125952              // [2 buf][4 grp][4 bbo][48f]; grp stride 800
#define H2_B  132352
#define XD_B  138752              // [2 buf][4 grp][4 bbo][16f]; grp stride 288
#define SMEM_BYTES 141056

#define HROWB 192                 // bytes per bbo row (48 floats, aligned)
#define HGSTR 800                 // grp stride: 800 % 128 == 32 -> lines at 0/32/64/96
#define HBUF  3200                // 4 * 800
#define XROWB 64
#define XGSTR 288                 // 288 % 128 == 32
#define XBUF  1152                // 4 * 288

__device__ __forceinline__ float fsig(float x) {
    return __fdividef(1.0f, 1.0f + __expf(-x));
}
__device__ __forceinline__ float ftanh_(float x) {
    return __fdividef(2.0f, 1.0f + __expf(-2.0f * x)) - 1.0f;
}
__device__ __forceinline__ void ffma2(ull& a, ull w, ull h) {
    asm("fma.rn.f32x2 %0, %1, %2, %0;" : "+l"(a) : "l"(w), "l"(h));
}
__device__ __forceinline__ float2 unpk(ull v) {
    float2 r;
    asm("mov.b64 {%0, %1}, %2;" : "=f"(r.x), "=f"(r.y) : "l"(v));
    return r;
}
__device__ __forceinline__ ull pk2(float a, float b) {
    ull d;
    asm("mov.b64 %0, {%1, %2};" : "=l"(d) : "f"(a), "f"(b));
    return d;
}

__global__ void __launch_bounds__(NTHREADS, 1)
lstm2_kernel(const float* __restrict__ x,
             const float* __restrict__ Wih0, const float* __restrict__ Whh0,
             const float* __restrict__ bih0, const float* __restrict__ bhh0,
             const float* __restrict__ Wih1, const float* __restrict__ Whh1,
             const float* __restrict__ bih1, const float* __restrict__ bhh1,
             const float* __restrict__ fcw,  const float* __restrict__ fcb,
             float* __restrict__ out)
{
    extern __shared__ char sm[];
    float* smf = (float*)sm;
    const int tid = threadIdx.x;

    // ---- repack W1I: [8kp][96jj2][16B] ----
    for (int i = tid; i < 8*96*4; i += NTHREADS) {
        int f = i & 3, jj2 = (i >> 2) % 96, kp = i / 384;
        int j = jj2 >> 1, gp = jj2 & 1;
        int gate = gp*2 + (f >> 1), k = kp*2 + (f & 1);
        smf[(W1I_B >> 2) + i] = Wih0[(gate*HH + j)*DD + k];
    }
    // ---- repack WR: [24kp][96jj2][3mat][16B] (Whh0, Wih1, Whh1) ----
    for (int i = tid; i < 24*96*3*4; i += NTHREADS) {
        int f = i & 3, m = (i >> 2) % 3, jj2 = (i / 12) % 96, kp = i / 1152;
        int j = jj2 >> 1, gp = jj2 & 1;
        int gate = gp*2 + (f >> 1), k = kp*2 + (f & 1);
        int r = (gate*HH + j)*HH + k;
        smf[(WR_B >> 2) + i] = (m == 0) ? Whh0[r] : (m == 1) ? Wih1[r] : Whh1[r];
    }
    // ---- biases ----
    for (int i = tid; i < 96*4; i += NTHREADS) {
        int f = i & 3, jj2 = i >> 2;
        int j = jj2 >> 1, gp = jj2 & 1;
        int gate = gp*2 + (f >> 1);
        float v1 = (f & 1) ? 0.f : (bih0[gate*HH + j] + bhh0[gate*HH + j]);
        float v2 = (f & 1) ? 0.f : (bih1[gate*HH + j] + bhh1[gate*HH + j]);
        smf[(BB1_B >> 2) + i] = v1;
        smf[(BB2_B >> 2) + i] = v2;
    }
    // ---- zero h region (both layers, both bufs, incl. pad) ----
    for (int i = tid; i < (4*HBUF) >> 2; i += NTHREADS)
        smf[(H1_B >> 2) + i] = 0.f;

    // ---- lane mapping: gp=b0, jsub=b1-2, grp=b3-4 ----
    const int gp   = tid & 1;
    const int jsub = (tid >> 1) & 3;
    const int grp  = (tid >> 3) & 3;
    const int w    = tid >> 5;
    const int j    = w * 4 + jsub;
    const int jj2  = j * 2 + gp;
    const int bl0  = grp * NBI;

    const float* xg = x + ((long)blockIdx.x * NB) * (long)(TT*DD);
    const int xb_ = tid >> 4, xd = tid & 15;     // global bb, element
    const int xact = (tid < NB*DD);
    const int xoff = (xb_ >> 2)*XGSTR + (xb_ & 3)*XROWB + xd*4;

    if (xact)
        *(float*)(sm + XD_B + xoff) = xg[(long)xb_*(TT*DD) + xd];
    __syncthreads();

    const char* pWI = sm + W1I_B + jj2*16;
    const char* pWR = sm + WR_B + jj2*48;
    const ulonglong2 b1 = *(const ulonglong2*)(sm + BB1_B + jj2*16);
    const ulonglong2 b2 = *(const ulonglong2*)(sm + BB2_B + jj2*16);

    float c1[2] = {0.f, 0.f};
    float c2[2] = {0.f, 0.f};

    for (int t = 0; t <= TT; ++t) {
        const int cur = t & 1, prv = cur ^ 1;

        float xpre = 0.f;
        if (t + 1 < TT && xact)
            xpre = xg[(long)xb_*(TT*DD) + (long)(t+1)*DD + xd];

        ull a1I[NBI], a1F[NBI], a2I[NBI], a2F[NBI];
        #pragma unroll
        for (int bb = 0; bb < NBI; ++bb) {
            a1I[bb] = b1.x; a1F[bb] = b1.y;
            a2I[bb] = b2.x; a2F[bb] = b2.y;
        }

        // ===== layer1 input: x =====
        {
            const char* xb = sm + XD_B + cur*XBUF + grp*XGSTR;
            #pragma unroll
            for (int kx = 0; kx < 4; ++kx) {
                const ulonglong2 w0 = *(const ulonglong2*)(pWI + (2*kx  )*1536);
                const ulonglong2 w1 = *(const ulonglong2*)(pWI + (2*kx+1)*1536);
                #pragma unroll
                for (int bb = 0; bb < NBI; ++bb) {
                    const ulonglong2 xv = *(const ulonglong2*)(xb + bb*XROWB + kx*16);
                    ffma2(a1I[bb], w0.x, xv.x); ffma2(a1F[bb], w0.y, xv.x);
                    ffma2(a1I[bb], w1.x, xv.y); ffma2(a1F[bb], w1.y, xv.y);
                }
            }
        }

        // ===== fused recurrent: W1R@h1[t-1], W2I@h1[t-1], W2R@h2[t-2] =====
        {
            const char* h1b = sm + H1_B + prv*HBUF + grp*HGSTR;
            const char* h2b = sm + H2_B + cur*HBUF + grp*HGSTR;
            #pragma unroll 3
            for (int kb = 0; kb < 12; ++kb) {
                const char* wb = pWR + kb*9216;
                const ulonglong2 wa0 = *(const ulonglong2*)(wb);
                const ulonglong2 wb0 = *(const ulonglong2*)(wb + 16);
                const ulonglong2 wc0 = *(const ulonglong2*)(wb + 32);
                const ulonglong2 wa1 = *(const ulonglong2*)(wb + 4608);
                const ulonglong2 wb1 = *(const ulonglong2*)(wb + 4624);
                const ulonglong2 wc1 = *(const ulonglong2*)(wb + 4640);
                #pragma unroll
                for (int bb = 0; bb < NBI; ++bb) {
                    const ulonglong2 h1v = *(const ulonglong2*)(h1b + bb*HROWB + kb*16);
                    const ulonglong2 h2v = *(const ulonglong2*)(h2b + bb*HROWB + kb*16);
                    ffma2(a1I[bb], wa0.x, h1v.x); ffma2(a1F[bb], wa0.y, h1v.x);
                    ffma2(a1I[bb], wa1.x, h1v.y); ffma2(a1F[bb], wa1.y, h1v.y);
                    ffma2(a2I[bb], wb0.x, h1v.x); ffma2(a2F[bb], wb0.y, h1v.x);
                    ffma2(a2I[bb], wb1.x, h1v.y); ffma2(a2F[bb], wb1.y, h1v.y);
                    ffma2(a2I[bb], wc0.x, h2v.x); ffma2(a2F[bb], wc0.y, h2v.x);
                    ffma2(a2I[bb], wc1.x, h2v.y); ffma2(a2F[bb], wc1.y, h2v.y);
                }
            }
        }

        char* h1n = sm + H1_B + cur*HBUF + grp*HGSTR;
        char* h2n = sm + H2_B + prv*HBUF + grp*HGSTR;

        if (t > 0 && t < TT) {
            // ===== steady state: both epilogues fused =====
            ull p1[NBI], e1[NBI], p2[NBI], e2[NBI];
            #pragma unroll
            for (int bb = 0; bb < NBI; ++bb) {
                float2 v1I = unpk(a1I[bb]), v1F = unpk(a1F[bb]);
                float2 v2I = unpk(a2I[bb]), v2F = unpk(a2F[bb]);
                p1[bb] = pk2(v1I.x + v1I.y, v1F.x + v1F.y);
                p2[bb] = pk2(v2I.x + v2I.y, v2F.x + v2F.y);
            }
            #pragma unroll
            for (int bb = 0; bb < NBI; ++bb) {
                e1[bb] = __shfl_xor_sync(0xFFFFFFFFu, p1[bb], 1);
                e2[bb] = __shfl_xor_sync(0xFFFFFFFFu, p2[bb], 1);
            }
            #pragma unroll
            for (int o = 0; o < 2; ++o) {
                const int bb = gp*2 + o;
                float2 pIF1 = unpk(gp ? e1[bb] : p1[bb]);
                float2 pGO1 = unpk(gp ? p1[bb] : e1[bb]);
                float2 pIF2 = unpk(gp ? e2[bb] : p2[bb]);
                float2 pGO2 = unpk(gp ? p2[bb] : e2[bb]);
                float iv1 = fsig(pIF1.x), iv2 = fsig(pIF2.x);
                float fv1 = fsig(pIF1.y), fv2 = fsig(pIF2.y);
                float gv1 = ftanh_(pGO1.x), gv2 = ftanh_(pGO2.x);
                float ov1 = fsig(pGO1.y),  ov2 = fsig(pGO2.y);
                c1[o] = fmaf(fv1, c1[o], iv1 * gv1);
                c2[o] = fmaf(fv2, c2[o], iv2 * gv2);
                *(float*)(h1n + bb*HROWB + j*4) = ov1 * ftanh_(c1[o]);
                *(float*)(h2n + bb*HROWB + j*4) = ov2 * ftanh_(c2[o]);
            }
        } else if (t < TT) {
            // t == 0: layer1 only
            ull p1[NBI], e1[NBI];
            #pragma unroll
            for (int bb = 0; bb < NBI; ++bb) {
                float2 vI = unpk(a1I[bb]), vF = unpk(a1F[bb]);
                p1[bb] = pk2(vI.x + vI.y, vF.x + vF.y);
            }
            #pragma unroll
            for (int bb = 0; bb < NBI; ++bb)
                e1[bb] = __shfl_xor_sync(0xFFFFFFFFu, p1[bb], 1);
            #pragma unroll
            for (int o = 0; o < 2; ++o) {
                const int bb = gp*2 + o;
                float2 pIF = unpk(gp ? e1[bb] : p1[bb]);
                float2 pGO = unpk(gp ? p1[bb] : e1[bb]);
                float iv = fsig(pIF.x), fv = fsig(pIF.y);
                float gv = ftanh_(pGO.x), ov = fsig(pGO.y);
                c1[o] = fmaf(fv, c1[o], iv * gv);
                *(float*)(h1n + bb*HROWB + j*4) = ov * ftanh_(c1[o]);
            }
        } else {
            // t == TT: layer2 only
            ull p2[NBI], e2[NBI];
            #pragma unroll
            for (int bb = 0; bb < NBI; ++bb) {
                float2 vI = unpk(a2I[bb]), vF = unpk(a2F[bb]);
                p2[bb] = pk2(vI.x + vI.y, vF.x + vF.y);
            }
            #pragma unroll
            for (int bb = 0; bb < NBI; ++bb)
                e2[bb] = __shfl_xor_sync(0xFFFFFFFFu, p2[bb], 1);
            #pragma unroll
            for (int o = 0; o < 2; ++o) {
                const int bb = gp*2 + o;
                float2 pIF = unpk(gp ? e2[bb] : p2[bb]);
                float2 pGO = unpk(gp ? p2[bb] : e2[bb]);
                float iv = fsig(pIF.x), fv = fsig(pIF.y);
                float gv = ftanh_(pGO.x), ov = fsig(pGO.y);
                c2[o] = fmaf(fv, c2[o], iv * gv);
                *(float*)(h2n + bb*HROWB + j*4) = ov * ftanh_(c2[o]);
            }
        }

        if (t + 1 < TT && xact)
            *(float*)(sm + XD_B + prv*XBUF + xoff) = xpre;
        __syncthreads();
    }

    // ===== final FC + sigmoid: h2[511] in buf 1 =====
    if (tid < NB) {
        const float* h2f = (const float*)(sm + H2_B + HBUF
                                          + (tid >> 2)*HGSTR + (tid & 3)*HROWB);
        float acc = fcb[0];
        #pragma unroll
        for (int jj = 0; jj < HH; ++jj)
            acc = fmaf(h2f[jj], fcw[jj], acc);
        out[blockIdx.x * NB + tid] = fsig(acc);
    }
}

extern "C" void kernel_launch(void* const* d_in, const int* in_sizes, int n_in,
                              void* d_out, int out_size) {
    (void)in_sizes; (void)n_in; (void)out_size;
    cudaFuncSetAttribute(lstm2_kernel,
                         cudaFuncAttributeMaxDynamicSharedMemorySize, SMEM_BYTES);
    lstm2_kernel<<<NCTA, NTHREADS, SMEM_BYTES>>>(
        (const float*)d_in[0],
        (const float*)d_in[1], (const float*)d_in[2],
        (const float*)d_in[3], (const float*)d_in[4],
        (const float*)d_in[5], (const float*)d_in[6],
        (const float*)d_in[7], (const float*)d_in[8],
        (const float*)d_in[9], (const float*)d_in[10],
        (float*)d_out);
}

// round 9
// speedup vs baseline: 1.2514x; 1.1314x over previous
#include <cuda_runtime.h>

// Problem constants
#define TT 512
#define DD 16
#define HH 48
#define NB 16
#define NBI 4
#define NTHREADS 384
#define NCTA 128

typedef unsigned long long ull;

// SMEM byte offsets
#define W1I_B 0                   // [8 kp][96 jj2][16B]
#define WR_B  12288               // [24 kp][96 jj2][3 mat][16B]
#define BB1_B 122880              // [96 jj2][16B] {b_g0,0,b_g1,0}
#define BB2_B 124416
#define H1_B  125952              // [2 buf][4 grp][4 bbo][48f]; grp stride 832
#define H2_B  132608
#define XD_B  139264              // [2 buf][4 grp][4 bbo][16f]; grp stride 320
#define SMEM_BYTES 141824

#define HROWB 192                 // 48 floats
#define HGSTR 832                 // 832 % 128 == 64 -> warp's 2 grp lines bank-disjoint
#define HBUF  3328                // 4 * 832
#define XROWB 64
#define XGSTR 320                 // 320 % 128 == 64
#define XBUF  1280                // 4 * 320

__device__ __forceinline__ float fsig(float x) {
    return __fdividef(1.0f, 1.0f + __expf(-x));
}
__device__ __forceinline__ float ftanh_(float x) {
    return __fdividef(2.0f, 1.0f + __expf(-2.0f * x)) - 1.0f;
}
__device__ __forceinline__ void ffma2(ull& a, ull w, ull h) {
    asm("fma.rn.f32x2 %0, %1, %2, %0;" : "+l"(a) : "l"(w), "l"(h));
}
__device__ __forceinline__ float2 unpk(ull v) {
    float2 r;
    asm("mov.b64 {%0, %1}, %2;" : "=f"(r.x), "=f"(r.y) : "l"(v));
    return r;
}
__device__ __forceinline__ ull pk2(float a, float b) {
    ull d;
    asm("mov.b64 %0, {%1, %2};" : "=l"(d) : "f"(a), "f"(b));
    return d;
}
__device__ __forceinline__ void half_bar(int id) {
    asm volatile("bar.sync %0, 192;" :: "r"(id) : "memory");
}

__global__ void __launch_bounds__(NTHREADS, 1)
lstm2_kernel(const float* __restrict__ x,
             const float* __restrict__ Wih0, const float* __restrict__ Whh0,
             const float* __restrict__ bih0, const float* __restrict__ bhh0,
             const float* __restrict__ Wih1, const float* __restrict__ Whh1,
             const float* __restrict__ bih1, const float* __restrict__ bhh1,
             const float* __restrict__ fcw,  const float* __restrict__ fcb,
             float* __restrict__ out)
{
    extern __shared__ char sm[];
    float* smf = (float*)sm;
    const int tid = threadIdx.x;

    // ---- repack W1I: [8kp][96jj2][16B] ----
    for (int i = tid; i < 8*96*4; i += NTHREADS) {
        int f = i & 3, jj2 = (i >> 2) % 96, kp = i / 384;
        int j = jj2 >> 1, gp = jj2 & 1;
        int gate = gp*2 + (f >> 1), k = kp*2 + (f & 1);
        smf[(W1I_B >> 2) + i] = Wih0[(gate*HH + j)*DD + k];
    }
    // ---- repack WR: [24kp][96jj2][3mat][16B] (Whh0, Wih1, Whh1) ----
    for (int i = tid; i < 24*96*3*4; i += NTHREADS) {
        int f = i & 3, m = (i >> 2) % 3, jj2 = (i / 12) % 96, kp = i / 1152;
        int j = jj2 >> 1, gp = jj2 & 1;
        int gate = gp*2 + (f >> 1), k = kp*2 + (f & 1);
        int r = (gate*HH + j)*HH + k;
        smf[(WR_B >> 2) + i] = (m == 0) ? Whh0[r] : (m == 1) ? Wih1[r] : Whh1[r];
    }
    // ---- biases ----
    for (int i = tid; i < 96*4; i += NTHREADS) {
        int f = i & 3, jj2 = i >> 2;
        int j = jj2 >> 1, gp = jj2 & 1;
        int gate = gp*2 + (f >> 1);
        float v1 = (f & 1) ? 0.f : (bih0[gate*HH + j] + bhh0[gate*HH + j]);
        float v2 = (f & 1) ? 0.f : (bih1[gate*HH + j] + bhh1[gate*HH + j]);
        smf[(BB1_B >> 2) + i] = v1;
        smf[(BB2_B >> 2) + i] = v2;
    }
    // ---- zero h region ----
    for (int i = tid; i < (4*HBUF) >> 2; i += NTHREADS)
        smf[(H1_B >> 2) + i] = 0.f;

    // ---- lane mapping (R5-style): gp=b0, jl=b1-3, grpl=b4; half by warp ----
    const int gp   = tid & 1;
    const int jl   = (tid >> 1) & 7;
    const int grpl = (tid >> 4) & 1;
    const int w    = tid >> 5;
    const int half = (tid >= 192);
    const int j    = (w % 6) * 8 + jl;
    const int grp  = half * 2 + grpl;
    const int jj2  = j * 2 + gp;
    const int barid = 1 + half;
    const int htid  = tid - half * 192;

    const float* xg = x + ((long)blockIdx.x * NB) * (long)(TT*DD);
    // per-half x staging: 128 threads of each half stage its 8 batch rows
    const int xact = (htid < 128);
    const int xb_  = half*8 + (htid >> 4);
    const int xd   = htid & 15;
    const int xoff = (xb_ >> 2)*XGSTR + (xb_ & 3)*XROWB + xd*4;

    if (xact)
        *(float*)(sm + XD_B + xoff) = xg[(long)xb_*(TT*DD) + xd];
    __syncthreads();

    const char* pWI = sm + W1I_B + jj2*16;
    const char* pWR = sm + WR_B + jj2*48;
    const ulonglong2 b1 = *(const ulonglong2*)(sm + BB1_B + jj2*16);
    const ulonglong2 b2 = *(const ulonglong2*)(sm + BB2_B + jj2*16);

    float c1[2] = {0.f, 0.f};
    float c2[2] = {0.f, 0.f};

    for (int t = 0; t <= TT; ++t) {
        const int cur = t & 1, prv = cur ^ 1;

        float xpre = 0.f;
        if (t + 1 < TT && xact)
            xpre = xg[(long)xb_*(TT*DD) + (long)(t+1)*DD + xd];

        ull a1I[NBI], a1F[NBI], a2I[NBI], a2F[NBI];
        #pragma unroll
        for (int bb = 0; bb < NBI; ++bb) {
            a1I[bb] = b1.x; a1F[bb] = b1.y;
            a2I[bb] = b2.x; a2F[bb] = b2.y;
        }

        // ===== layer1 input: x (k-parity packed) =====
        {
            const char* xb = sm + XD_B + cur*XBUF + grp*XGSTR;
            #pragma unroll
            for (int kx = 0; kx < 4; ++kx) {
                const ulonglong2 w0 = *(const ulonglong2*)(pWI + (2*kx  )*1536);
                const ulonglong2 w1 = *(const ulonglong2*)(pWI + (2*kx+1)*1536);
                #pragma unroll
                for (int bb = 0; bb < NBI; ++bb) {
                    const ulonglong2 xv = *(const ulonglong2*)(xb + bb*XROWB + kx*16);
                    ffma2(a1I[bb], w0.x, xv.x); ffma2(a1F[bb], w0.y, xv.x);
                    ffma2(a1I[bb], w1.x, xv.y); ffma2(a1F[bb], w1.y, xv.y);
                }
            }
        }

        // ===== fused recurrent: W1R@h1[t-1], W2I@h1[t-1], W2R@h2[t-2] =====
        {
            const char* h1b = sm + H1_B + prv*HBUF + grp*HGSTR;
            const char* h2b = sm + H2_B + cur*HBUF + grp*HGSTR;
            #pragma unroll 4
            for (int kb = 0; kb < 12; ++kb) {
                const char* wb = pWR + kb*9216;
                const ulonglong2 wa0 = *(const ulonglong2*)(wb);
                const ulonglong2 wb0 = *(const ulonglong2*)(wb + 16);
                const ulonglong2 wc0 = *(const ulonglong2*)(wb + 32);
                const ulonglong2 wa1 = *(const ulonglong2*)(wb + 4608);
                const ulonglong2 wb1 = *(const ulonglong2*)(wb + 4624);
                const ulonglong2 wc1 = *(const ulonglong2*)(wb + 4640);
                #pragma unroll
                for (int bb = 0; bb < NBI; ++bb) {
                    const ulonglong2 h1v = *(const ulonglong2*)(h1b + bb*HROWB + kb*16);
                    const ulonglong2 h2v = *(const ulonglong2*)(h2b + bb*HROWB + kb*16);
                    ffma2(a1I[bb], wa0.x, h1v.x); ffma2(a1F[bb], wa0.y, h1v.x);
                    ffma2(a1I[bb], wa1.x, h1v.y); ffma2(a1F[bb], wa1.y, h1v.y);
                    ffma2(a2I[bb], wb0.x, h1v.x); ffma2(a2F[bb], wb0.y, h1v.x);
                    ffma2(a2I[bb], wb1.x, h1v.y); ffma2(a2F[bb], wb1.y, h1v.y);
                    ffma2(a2I[bb], wc0.x, h2v.x); ffma2(a2F[bb], wc0.y, h2v.x);
                    ffma2(a2I[bb], wc1.x, h2v.y); ffma2(a2F[bb], wc1.y, h2v.y);
                }
            }
        }

        char* h1n = sm + H1_B + cur*HBUF + grp*HGSTR;
        char* h2n = sm + H2_B + prv*HBUF + grp*HGSTR;

        if (t > 0 && t < TT) {
            // ===== steady state: both epilogues fused =====
            ull p1[NBI], e1[NBI], p2[NBI], e2[NBI];
            #pragma unroll
            for (int bb = 0; bb < NBI; ++bb) {
                float2 v1I = unpk(a1I[bb]), v1F = unpk(a1F[bb]);
                float2 v2I = unpk(a2I[bb]), v2F = unpk(a2F[bb]);
                p1[bb] = pk2(v1I.x + v1I.y, v1F.x + v1F.y);
                p2[bb] = pk2(v2I.x + v2I.y, v2F.x + v2F.y);
            }
            #pragma unroll
            for (int bb = 0; bb < NBI; ++bb) {
                e1[bb] = __shfl_xor_sync(0xFFFFFFFFu, p1[bb], 1);
                e2[bb] = __shfl_xor_sync(0xFFFFFFFFu, p2[bb], 1);
            }
            #pragma unroll
            for (int o = 0; o < 2; ++o) {
                const int bb = gp*2 + o;
                float2 pIF1 = unpk(gp ? e1[bb] : p1[bb]);
                float2 pGO1 = unpk(gp ? p1[bb] : e1[bb]);
                float2 pIF2 = unpk(gp ? e2[bb] : p2[bb]);
                float2 pGO2 = unpk(gp ? p2[bb] : e2[bb]);
                float iv1 = fsig(pIF1.x), iv2 = fsig(pIF2.x);
                float fv1 = fsig(pIF1.y), fv2 = fsig(pIF2.y);
                float gv1 = ftanh_(pGO1.x), gv2 = ftanh_(pGO2.x);
                float ov1 = fsig(pGO1.y),  ov2 = fsig(pGO2.y);
                c1[o] = fmaf(fv1, c1[o], iv1 * gv1);
                c2[o] = fmaf(fv2, c2[o], iv2 * gv2);
                *(float*)(h1n + bb*HROWB + j*4) = ov1 * ftanh_(c1[o]);
                *(float*)(h2n + bb*HROWB + j*4) = ov2 * ftanh_(c2[o]);
            }
        } else if (t < TT) {
            // t == 0: layer1 only
            ull p1[NBI], e1[NBI];
            #pragma unroll
            for (int bb = 0; bb < NBI; ++bb) {
                float2 vI = unpk(a1I[bb]), vF = unpk(a1F[bb]);
                p1[bb] = pk2(vI.x + vI.y, vF.x + vF.y);
            }
            #pragma unroll
            for (int bb = 0; bb < NBI; ++bb)
                e1[bb] = __shfl_xor_sync(0xFFFFFFFFu, p1[bb], 1);
            #pragma unroll
            for (int o = 0; o < 2; ++o) {
                const int bb = gp*2 + o;
                float2 pIF = unpk(gp ? e1[bb] : p1[bb]);
                float2 pGO = unpk(gp ? p1[bb] : e1[bb]);
                float iv = fsig(pIF.x), fv = fsig(pIF.y);
                float gv = ftanh_(pGO.x), ov = fsig(pGO.y);
                c1[o] = fmaf(fv, c1[o], iv * gv);
                *(float*)(h1n + bb*HROWB + j*4) = ov * ftanh_(c1[o]);
            }
        } else {
            // t == TT: layer2 only
            ull p2[NBI], e2[NBI];
            #pragma unroll
            for (int bb = 0; bb < NBI; ++bb) {
                float2 vI = unpk(a2I[bb]), vF = unpk(a2F[bb]);
                p2[bb] = pk2(vI.x + vI.y, vF.x + vF.y);
            }
            #pragma unroll
            for (int bb = 0; bb < NBI; ++bb)
                e2[bb] = __shfl_xor_sync(0xFFFFFFFFu, p2[bb], 1);
            #pragma unroll
            for (int o = 0; o < 2; ++o) {
                const int bb = gp*2 + o;
                float2 pIF = unpk(gp ? e2[bb] : p2[bb]);
                float2 pGO = unpk(gp ? p2[bb] : e2[bb]);
                float iv = fsig(pIF.x), fv = fsig(pIF.y);
                float gv = ftanh_(pGO.x), ov = fsig(pGO.y);
                c2[o] = fmaf(fv, c2[o], iv * gv);
                *(float*)(h2n + bb*HROWB + j*4) = ov * ftanh_(c2[o]);
            }
        }

        if (t + 1 < TT && xact)
            *(float*)(sm + XD_B + prv*XBUF + xoff) = xpre;

        half_bar(barid);
    }

    __syncthreads();
    // ===== final FC + sigmoid: h2[511] in buf 1 =====
    if (tid < NB) {
        const float* h2f = (const float*)(sm + H2_B + HBUF
                                          + (tid >> 2)*HGSTR + (tid & 3)*HROWB);
        float acc = fcb[0];
        #pragma unroll
        for (int jj = 0; jj < HH; ++jj)
            acc = fmaf(h2f[jj], fcw[jj], acc);
        out[blockIdx.x * NB + tid] = fsig(acc);
    }
}

extern "C" void kernel_launch(void* const* d_in, const int* in_sizes, int n_in,
                              void* d_out, int out_size) {
    (void)in_sizes; (void)n_in; (void)out_size;
    cudaFuncSetAttribute(lstm2_kernel,
                         cudaFuncAttributeMaxDynamicSharedMemorySize, SMEM_BYTES);
    lstm2_kernel<<<NCTA, NTHREADS, SMEM_BYTES>>>(
        (const float*)d_in[0],
        (const float*)d_in[1], (const float*)d_in[2],
        (const float*)d_in[3], (const float*)d_in[4],
        (const float*)d_in[5], (const float*)d_in[6],
        (const float*)d_in[7], (const float*)d_in[8],
        (const float*)d_in[9], (const float*)d_in[10],
        (float*)d_out);
}

// round 10
// speedup vs baseline: 1.3176x; 1.0529x over previous
#include <cuda_runtime.h>

// Problem constants
#define TT 512
#define DD 16
#define HH 48
#define NB 16
#define NBI 4
#define NTHREADS 384
#define NCTA 128

typedef unsigned long long ull;

// SMEM byte offsets
#define W1I_B 0                   // [8 kp][96 jj2][16B]
#define WR_B  12288               // [24 kp][96 jj2][3 mat][16B]
#define BB1_B 122880              // [96 jj2][16B] {b_g0,0,b_g1,0}
#define BB2_B 124416
#define H1_B  125952              // [2 buf][4 grp][4 bbo][48f]; grp stride 832
#define H2_B  132608
#define XD_B  139264              // [2 buf][4 grp][4 bbo][16f]; grp stride 320
#define SMEM_BYTES 141824

#define HROWB 192
#define HGSTR 832
#define HBUF  3328
#define XROWB 64
#define XGSTR 320
#define XBUF  1280

__device__ __forceinline__ float fsig(float x) {
    return __fdividef(1.0f, 1.0f + __expf(-x));
}
__device__ __forceinline__ float ftanh_(float x) {
    return __fdividef(2.0f, 1.0f + __expf(-2.0f * x)) - 1.0f;
}
__device__ __forceinline__ void ffma2(ull& a, ull w, ull h) {
    asm("fma.rn.f32x2 %0, %1, %2, %0;" : "+l"(a) : "l"(w), "l"(h));
}
__device__ __forceinline__ float2 unpk(ull v) {
    float2 r;
    asm("mov.b64 {%0, %1}, %2;" : "=f"(r.x), "=f"(r.y) : "l"(v));
    return r;
}
__device__ __forceinline__ ull pk2(float a, float b) {
    ull d;
    asm("mov.b64 %0, {%1, %2};" : "=l"(d) : "f"(a), "f"(b));
    return d;
}
__device__ __forceinline__ void q_bar(int id) {
    asm volatile("bar.sync %0, 96;" :: "r"(id) : "memory");
}

__global__ void __launch_bounds__(NTHREADS, 1)
lstm2_kernel(const float* __restrict__ x,
             const float* __restrict__ Wih0, const float* __restrict__ Whh0,
             const float* __restrict__ bih0, const float* __restrict__ bhh0,
             const float* __restrict__ Wih1, const float* __restrict__ Whh1,
             const float* __restrict__ bih1, const float* __restrict__ bhh1,
             const float* __restrict__ fcw,  const float* __restrict__ fcb,
             float* __restrict__ out)
{
    extern __shared__ char sm[];
    float* smf = (float*)sm;
    const int tid = threadIdx.x;

    // ---- repack W1I: [8kp][96jj2][16B] ----
    for (int i = tid; i < 8*96*4; i += NTHREADS) {
        int f = i & 3, jj2 = (i >> 2) % 96, kp = i / 384;
        int j = jj2 >> 1, gp = jj2 & 1;
        int gate = gp*2 + (f >> 1), k = kp*2 + (f & 1);
        smf[(W1I_B >> 2) + i] = Wih0[(gate*HH + j)*DD + k];
    }
    // ---- repack WR: [24kp][96jj2][3mat][16B] (Whh0, Wih1, Whh1) ----
    for (int i = tid; i < 24*96*3*4; i += NTHREADS) {
        int f = i & 3, m = (i >> 2) % 3, jj2 = (i / 12) % 96, kp = i / 1152;
        int j = jj2 >> 1, gp = jj2 & 1;
        int gate = gp*2 + (f >> 1), k = kp*2 + (f & 1);
        int r = (gate*HH + j)*HH + k;
        smf[(WR_B >> 2) + i] = (m == 0) ? Whh0[r] : (m == 1) ? Wih1[r] : Whh1[r];
    }
    // ---- biases ----
    for (int i = tid; i < 96*4; i += NTHREADS) {
        int f = i & 3, jj2 = i >> 2;
        int j = jj2 >> 1, gp = jj2 & 1;
        int gate = gp*2 + (f >> 1);
        float v1 = (f & 1) ? 0.f : (bih0[gate*HH + j] + bhh0[gate*HH + j]);
        float v2 = (f & 1) ? 0.f : (bih1[gate*HH + j] + bhh1[gate*HH + j]);
        smf[(BB1_B >> 2) + i] = v1;
        smf[(BB2_B >> 2) + i] = v2;
    }
    // ---- zero h region ----
    for (int i = tid; i < (4*HBUF) >> 2; i += NTHREADS)
        smf[(H1_B >> 2) + i] = 0.f;

    // ---- quarter decomposition: 4 independent domains of 3 warps ----
    // quarter q = w/3 -> q's warps live on 3 different SMSPs; each SMSP mixes 3 quarters
    const int w    = tid >> 5;
    const int lane = tid & 31;
    const int q    = w / 3;            // 0..3 = batch group
    const int wq   = w % 3;            // warp within quarter
    const int gp   = lane & 1;
    const int j    = wq * 16 + (lane >> 1);
    const int jj2  = j * 2 + gp;
    const int grp  = q;
    const int barid = 1 + q;
    const int qtid  = wq * 32 + lane;  // 0..95 within quarter

    const float* xg = x + ((long)blockIdx.x * NB) * (long)(TT*DD);
    // per-quarter x staging: 64 threads stage the quarter's 4 batch rows
    const int xact = (qtid < 64);
    const int xb_  = q * 4 + (qtid >> 4);
    const int xd   = qtid & 15;
    const int xoff = (xb_ >> 2)*XGSTR + (xb_ & 3)*XROWB + xd*4;

    if (xact)
        *(float*)(sm + XD_B + xoff) = xg[(long)xb_*(TT*DD) + xd];
    __syncthreads();

    const char* pWI = sm + W1I_B + jj2*16;
    const char* pWR = sm + WR_B + jj2*48;
    const ulonglong2 b1 = *(const ulonglong2*)(sm + BB1_B + jj2*16);
    const ulonglong2 b2 = *(const ulonglong2*)(sm + BB2_B + jj2*16);

    float c1[2] = {0.f, 0.f};
    float c2[2] = {0.f, 0.f};

    for (int t = 0; t <= TT; ++t) {
        const int cur = t & 1, prv = cur ^ 1;

        float xpre = 0.f;
        if (t + 1 < TT && xact)
            xpre = xg[(long)xb_*(TT*DD) + (long)(t+1)*DD + xd];

        ull a1I[NBI], a1F[NBI], a2I[NBI], a2F[NBI];
        #pragma unroll
        for (int bb = 0; bb < NBI; ++bb) {
            a1I[bb] = b1.x; a1F[bb] = b1.y;
            a2I[bb] = b2.x; a2F[bb] = b2.y;
        }

        // ===== layer1 input: x (k-parity packed, broadcast loads) =====
        {
            const char* xb = sm + XD_B + cur*XBUF + grp*XGSTR;
            #pragma unroll
            for (int kx = 0; kx < 4; ++kx) {
                const ulonglong2 w0 = *(const ulonglong2*)(pWI + (2*kx  )*1536);
                const ulonglong2 w1 = *(const ulonglong2*)(pWI + (2*kx+1)*1536);
                #pragma unroll
                for (int bb = 0; bb < NBI; ++bb) {
                    const ulonglong2 xv = *(const ulonglong2*)(xb + bb*XROWB + kx*16);
                    ffma2(a1I[bb], w0.x, xv.x); ffma2(a1F[bb], w0.y, xv.x);
                    ffma2(a1I[bb], w1.x, xv.y); ffma2(a1F[bb], w1.y, xv.y);
                }
            }
        }

        // ===== fused recurrent: W1R@h1[t-1], W2I@h1[t-1], W2R@h2[t-2] =====
        {
            const char* h1b = sm + H1_B + prv*HBUF + grp*HGSTR;
            const char* h2b = sm + H2_B + cur*HBUF + grp*HGSTR;
            #pragma unroll 4
            for (int kb = 0; kb < 12; ++kb) {
                const char* wb = pWR + kb*9216;
                const ulonglong2 wa0 = *(const ulonglong2*)(wb);
                const ulonglong2 wb0 = *(const ulonglong2*)(wb + 16);
                const ulonglong2 wc0 = *(const ulonglong2*)(wb + 32);
                const ulonglong2 wa1 = *(const ulonglong2*)(wb + 4608);
                const ulonglong2 wb1 = *(const ulonglong2*)(wb + 4624);
                const ulonglong2 wc1 = *(const ulonglong2*)(wb + 4640);
                #pragma unroll
                for (int bb = 0; bb < NBI; ++bb) {
                    const ulonglong2 h1v = *(const ulonglong2*)(h1b + bb*HROWB + kb*16);
                    const ulonglong2 h2v = *(const ulonglong2*)(h2b + bb*HROWB + kb*16);
                    ffma2(a1I[bb], wa0.x, h1v.x); ffma2(a1F[bb], wa0.y, h1v.x);
                    ffma2(a1I[bb], wa1.x, h1v.y); ffma2(a1F[bb], wa1.y, h1v.y);
                    ffma2(a2I[bb], wb0.x, h1v.x); ffma2(a2F[bb], wb0.y, h1v.x);
                    ffma2(a2I[bb], wb1.x, h1v.y); ffma2(a2F[bb], wb1.y, h1v.y);
                    ffma2(a2I[bb], wc0.x, h2v.x); ffma2(a2F[bb], wc0.y, h2v.x);
                    ffma2(a2I[bb], wc1.x, h2v.y); ffma2(a2F[bb], wc1.y, h2v.y);
                }
            }
        }

        char* h1n = sm + H1_B + cur*HBUF + grp*HGSTR;
        char* h2n = sm + H2_B + prv*HBUF + grp*HGSTR;

        if (t > 0 && t < TT) {
            ull p1[NBI], e1[NBI], p2[NBI], e2[NBI];
            #pragma unroll
            for (int bb = 0; bb < NBI; ++bb) {
                float2 v1I = unpk(a1I[bb]), v1F = unpk(a1F[bb]);
                float2 v2I = unpk(a2I[bb]), v2F = unpk(a2F[bb]);
                p1[bb] = pk2(v1I.x + v1I.y, v1F.x + v1F.y);
                p2[bb] = pk2(v2I.x + v2I.y, v2F.x + v2F.y);
            }
            #pragma unroll
            for (int bb = 0; bb < NBI; ++bb) {
                e1[bb] = __shfl_xor_sync(0xFFFFFFFFu, p1[bb], 1);
                e2[bb] = __shfl_xor_sync(0xFFFFFFFFu, p2[bb], 1);
            }
            #pragma unroll
            for (int o = 0; o < 2; ++o) {
                const int bb = gp*2 + o;
                float2 pIF1 = unpk(gp ? e1[bb] : p1[bb]);
                float2 pGO1 = unpk(gp ? p1[bb] : e1[bb]);
                float2 pIF2 = unpk(gp ? e2[bb] : p2[bb]);
                float2 pGO2 = unpk(gp ? p2[bb] : e2[bb]);
                float iv1 = fsig(pIF1.x), iv2 = fsig(pIF2.x);
                float fv1 = fsig(pIF1.y), fv2 = fsig(pIF2.y);
                float gv1 = ftanh_(pGO1.x), gv2 = ftanh_(pGO2.x);
                float ov1 = fsig(pGO1.y),  ov2 = fsig(pGO2.y);
                c1[o] = fmaf(fv1, c1[o], iv1 * gv1);
                c2[o] = fmaf(fv2, c2[o], iv2 * gv2);
                *(float*)(h1n + bb*HROWB + j*4) = ov1 * ftanh_(c1[o]);
                *(float*)(h2n + bb*HROWB + j*4) = ov2 * ftanh_(c2[o]);
            }
        } else if (t < TT) {
            ull p1[NBI], e1[NBI];
            #pragma unroll
            for (int bb = 0; bb < NBI; ++bb) {
                float2 vI = unpk(a1I[bb]), vF = unpk(a1F[bb]);
                p1[bb] = pk2(vI.x + vI.y, vF.x + vF.y);
            }
            #pragma unroll
            for (int bb = 0; bb < NBI; ++bb)
                e1[bb] = __shfl_xor_sync(0xFFFFFFFFu, p1[bb], 1);
            #pragma unroll
            for (int o = 0; o < 2; ++o) {
                const int bb = gp*2 + o;
                float2 pIF = unpk(gp ? e1[bb] : p1[bb]);
                float2 pGO = unpk(gp ? p1[bb] : e1[bb]);
                float iv = fsig(pIF.x), fv = fsig(pIF.y);
                float gv = ftanh_(pGO.x), ov = fsig(pGO.y);
                c1[o] = fmaf(fv, c1[o], iv * gv);
                *(float*)(h1n + bb*HROWB + j*4) = ov * ftanh_(c1[o]);
            }
        } else {
            ull p2[NBI], e2[NBI];
            #pragma unroll
            for (int bb = 0; bb < NBI; ++bb) {
                float2 vI = unpk(a2I[bb]), vF = unpk(a2F[bb]);
                p2[bb] = pk2(vI.x + vI.y, vF.x + vF.y);
            }
            #pragma unroll
            for (int bb = 0; bb < NBI; ++bb)
                e2[bb] = __shfl_xor_sync(0xFFFFFFFFu, p2[bb], 1);
            #pragma unroll
            for (int o = 0; o < 2; ++o) {
                const int bb = gp*2 + o;
                float2 pIF = unpk(gp ? e2[bb] : p2[bb]);
                float2 pGO = unpk(gp ? p2[bb] : e2[bb]);
                float iv = fsig(pIF.x), fv = fsig(pIF.y);
                float gv = ftanh_(pGO.x), ov = fsig(pGO.y);
                c2[o] = fmaf(fv, c2[o], iv * gv);
                *(float*)(h2n + bb*HROWB + j*4) = ov * ftanh_(c2[o]);
            }
        }

        if (t + 1 < TT && xact)
            *(float*)(sm + XD_B + prv*XBUF + xoff) = xpre;

        q_bar(barid);
    }

    __syncthreads();
    // ===== final FC + sigmoid: h2[511] in buf 1 =====
    if (tid < NB) {
        const float* h2f = (const float*)(sm + H2_B + HBUF
                                          + (tid >> 2)*HGSTR + (tid & 3)*HROWB);
        float acc = fcb[0];
        #pragma unroll
        for (int jj = 0; jj < HH; ++jj)
            acc = fmaf(h2f[jj], fcw[jj], acc);
        out[blockIdx.x * NB + tid] = fsig(acc);
    }
}

extern "C" void kernel_launch(void* const* d_in, const int* in_sizes, int n_in,
                              void* d_out, int out_size) {
    (void)in_sizes; (void)n_in; (void)out_size;
    cudaFuncSetAttribute(lstm2_kernel,
                         cudaFuncAttributeMaxDynamicSharedMemorySize, SMEM_BYTES);
    lstm2_kernel<<<NCTA, NTHREADS, SMEM_BYTES>>>(
        (const float*)d_in[0],
        (const float*)d_in[1], (const float*)d_in[2],
        (const float*)d_in[3], (const float*)d_in[4],
        (const float*)d_in[5], (const float*)d_in[6],
        (const float*)d_in[7], (const float*)d_in[8],
        (const float*)d_in[9], (const float*)d_in[10],
        (float*)d_out);
}